// round 15
// baseline (speedup 1.0000x reference)
#include <cuda_runtime.h>
#include <cuda_bf16.h>
#include <cuda_fp16.h>
#include <cstdint>

#define IN_DIM    200
#define OUT_DIMX  2000
#define BATCHN    512
#define OUT_CH    32
#define KERN      9
#define L_OUTN    1992
#define FC_LENN   (OUT_CH * L_OUTN)     // 63744
#define NUM_ENTSN 100000
#define EPSV      1e-5f
#define ZSPLIT    37                    // fc: grid (2,2,37) = 148 CTAs = 1 wave
#define ZCHUNK    1728                  // 37*1728 = 63936 >= 63744 (global K guard)
#define KPAD2     224

// ---------------- device scratch ----------------
__device__ __align__(128) __nv_bfloat16 g_eWTb[OUT_DIMX * IN_DIM];
__device__ __align__(128) __nv_bfloat16 g_x0b[BATCHN * KPAD2];
__device__ __align__(128) float g_xa [BATCHN * OUT_DIMX];
__device__ __align__(128) __nv_bfloat16 g_cbf[(size_t)BATCHN * FC_LENN + 512];
__device__ __align__(128) float g_Pf [(size_t)ZSPLIT * BATCHN * IN_DIM];
__device__ __align__(128) float g_y  [BATCHN * IN_DIM];
__device__ __align__(128) __half g_zh[BATCHN * KPAD2];
__device__ float g_s1[OUT_CH * BATCHN];
__device__ float g_s2[OUT_CH * BATCHN];
__device__ float g_alpha[OUT_CH];
__device__ float g_betap[OUT_CH];

// ---------------- helpers ----------------
__device__ __forceinline__ uint32_t smem_u32(const void* p) {
    uint32_t a;
    asm("{ .reg .u64 t; cvta.to.shared.u64 t, %1; cvt.u32.u64 %0, t; }" : "=r"(a) : "l"(p));
    return a;
}
__device__ __forceinline__ void ldsm_x4(uint32_t* r, uint32_t addr) {
    asm volatile("ldmatrix.sync.aligned.m8n8.x4.shared.b16 {%0,%1,%2,%3}, [%4];"
                 : "=r"(r[0]), "=r"(r[1]), "=r"(r[2]), "=r"(r[3]) : "r"(addr));
}
__device__ __forceinline__ void mma_bf16(float* c, const uint32_t* a, const uint32_t* b) {
    asm volatile("mma.sync.aligned.m16n8k16.row.col.f32.bf16.bf16.f32 "
                 "{%0,%1,%2,%3}, {%4,%5,%6,%7}, {%8,%9}, {%0,%1,%2,%3};"
                 : "+f"(c[0]), "+f"(c[1]), "+f"(c[2]), "+f"(c[3])
                 : "r"(a[0]), "r"(a[1]), "r"(a[2]), "r"(a[3]), "r"(b[0]), "r"(b[1]));
}
__device__ __forceinline__ void mma_f16acc(uint32_t* c, const uint32_t* a, const uint32_t* b) {
    asm volatile("mma.sync.aligned.m16n8k16.row.col.f16.f16.f16.f16 "
                 "{%0,%1}, {%2,%3,%4,%5}, {%6,%7}, {%0,%1};"
                 : "+r"(c[0]), "+r"(c[1])
                 : "r"(a[0]), "r"(a[1]), "r"(a[2]), "r"(a[3]), "r"(b[0]), "r"(b[1]));
}
__device__ __forceinline__ float blockReduceSum(float v, float* s) {
    __syncthreads();
    #pragma unroll
    for (int o = 16; o; o >>= 1) v += __shfl_down_sync(0xffffffffu, v, o);
    int w = threadIdx.x >> 5, l = threadIdx.x & 31;
    if (l == 0) s[w] = v;
    __syncthreads();
    int nw = blockDim.x >> 5;
    if (w == 0) {
        float r = (l < nw) ? s[l] : 0.f;
        #pragma unroll
        for (int o = 16; o; o >>= 1) r += __shfl_down_sync(0xffffffffu, r, o);
        if (l == 0) s[0] = r;
    }
    __syncthreads();
    return s[0];
}

// ---------------- tiled transpose: e_W -> bf16 eWT [2000,200] ------
__global__ void k_transpose(const float* __restrict__ W) {
    __shared__ float tile[32][33];
    int n0 = blockIdx.x * 32, k0 = blockIdx.y * 32;
    int tx = threadIdx.x, ty = threadIdx.y;
    #pragma unroll
    for (int dy = 0; dy < 32; dy += 8) {
        int k = k0 + ty + dy, n = n0 + tx;
        tile[ty + dy][tx] = (k < IN_DIM && n < OUT_DIMX) ? W[k * OUT_DIMX + n] : 0.f;
    }
    __syncthreads();
    #pragma unroll
    for (int dy = 0; dy < 32; dy += 8) {
        int n = n0 + ty + dy, k = k0 + tx;
        if (n < OUT_DIMX && k < IN_DIM)
            g_eWTb[n * IN_DIM + k] = __float2bfloat16(tile[tx][ty + dy]);
    }
}

// ---------------- gather + bn0 -> bf16 padded ----------------
__global__ void k_bn0(const float* __restrict__ E, const int* __restrict__ e1,
                      const float* __restrict__ g, const float* __restrict__ bt) {
    int f = blockIdx.x, b = threadIdx.x;
    if (f >= IN_DIM) {
        g_x0b[b * KPAD2 + f] = __nv_bfloat16(0.f);
        return;
    }
    float v = E[(size_t)e1[b] * IN_DIM + f];
    __shared__ float sr[32];
    float s1 = blockReduceSum(v, sr);
    float s2 = blockReduceSum(v * v, sr);
    float m = s1 * (1.f / BATCHN);
    float var = s2 * (1.f / BATCHN) - m * m;
    g_x0b[b * KPAD2 + f] =
        __float2bfloat16((v - m) * rsqrtf(var + EPSV) * g[f] + bt[f]);
}

// ---------------- bn1 stats via windowed autocorrelation ----------
__global__ __launch_bounds__(256) void k_statsA(const float* __restrict__ R,
                                                const int* __restrict__ ridx) {
    int b = blockIdx.x, t = threadIdx.x;
    __shared__ __align__(16) float sx[OUT_DIMX];
    __shared__ float red[8][54];
    __shared__ float TG[54];
    for (int i = t; i < OUT_DIMX; i += 256) sx[i] = g_xa[(size_t)b * OUT_DIMX + i];
    __syncthreads();
    float acc[54];
    #pragma unroll
    for (int i = 0; i < 54; i++) acc[i] = 0.f;
    for (int grp = t; grp < L_OUTN / 4; grp += 256) {
        int l4 = grp * 4;
        float w[12];
        float4 v0 = *(const float4*)(sx + l4);
        float4 v1 = *(const float4*)(sx + l4 + 4);
        float4 v2 = *(const float4*)(sx + l4 + 8);
        w[0]=v0.x; w[1]=v0.y; w[2]=v0.z; w[3]=v0.w;
        w[4]=v1.x; w[5]=v1.y; w[6]=v1.z; w[7]=v1.w;
        w[8]=v2.x; w[9]=v2.y; w[10]=v2.z; w[11]=v2.w;
        #pragma unroll
        for (int j = 0; j < 4; j++) {
            #pragma unroll
            for (int k = 0; k < KERN; k++) acc[k] += w[j + k];
            int p = 9;
            #pragma unroll
            for (int k = 0; k < KERN; k++)
                #pragma unroll
                for (int k2 = k; k2 < KERN; k2++) acc[p++] += w[j + k] * w[j + k2];
        }
    }
    #pragma unroll
    for (int i = 0; i < 54; i++) {
        float v = acc[i];
        #pragma unroll
        for (int o = 16; o; o >>= 1) v += __shfl_down_sync(0xffffffffu, v, o);
        if ((t & 31) == 0) red[t >> 5][i] = v;
    }
    __syncthreads();
    if (t < 54) {
        float s = 0.f;
        #pragma unroll
        for (int w2 = 0; w2 < 8; w2++) s += red[w2][t];
        TG[t] = s;
    }
    __syncthreads();
    if (t < OUT_CH) {
        const float* Rb = R + (size_t)ridx[b] * OUT_CH * KERN + t * KERN;
        float r[KERN];
        #pragma unroll
        for (int k = 0; k < KERN; k++) r[k] = Rb[k];
        float s1 = 0.f, s2 = 0.f;
        #pragma unroll
        for (int k = 0; k < KERN; k++) s1 += r[k] * TG[k];
        int p = 9;
        #pragma unroll
        for (int k = 0; k < KERN; k++)
            #pragma unroll
            for (int k2 = k; k2 < KERN; k2++) {
                float c = (k2 == k) ? 1.f : 2.f;
                s2 += c * r[k] * r[k2] * TG[p++];
            }
        g_s1[t * BATCHN + b] = s1;
        g_s2[t * BATCHN + b] = s2;
    }
}
__global__ void k_statsB(const float* __restrict__ g1, const float* __restrict__ b1) {
    int o = blockIdx.x;
    __shared__ float sr[32];
    float s1 = blockReduceSum(g_s1[o * BATCHN + threadIdx.x], sr);
    float s2 = blockReduceSum(g_s2[o * BATCHN + threadIdx.x], sr);
    if (threadIdx.x == 0) {
        float Nf = (float)BATCHN * (float)L_OUTN;
        float m = s1 / Nf;
        float var = s2 / Nf - m * m;
        float a = rsqrtf(var + EPSV) * g1[o];
        g_alpha[o] = a;
        g_betap[o] = b1[o] - m * a;
    }
}

// ---------------- conv1d + bn1-affine -> bf16 (channel-split) ----
#define CSPLIT 4
#define CH_PER (OUT_CH / CSPLIT)
__global__ __launch_bounds__(256) void k_conv(const float* __restrict__ R,
                                              const int* __restrict__ ridx) {
    int b = blockIdx.x;
    int o0 = blockIdx.y * CH_PER;
    __shared__ float sx[OUT_DIMX];
    for (int i = threadIdx.x; i < OUT_DIMX; i += 256)
        sx[i] = g_xa[(size_t)b * OUT_DIMX + i];
    __syncthreads();
    const float* Rb = R + (size_t)ridx[b] * OUT_CH * KERN;
    #pragma unroll
    for (int oo = 0; oo < CH_PER; oo++) {
        int o = o0 + oo;
        float r[KERN];
        #pragma unroll
        for (int k = 0; k < KERN; k++) r[k] = Rb[o * KERN + k];
        float al = g_alpha[o], be = g_betap[o];
        __nv_bfloat162* cp2 = (__nv_bfloat162*)(g_cbf + (size_t)b * FC_LENN + o * L_OUTN);
        for (int i = threadIdx.x; i < L_OUTN / 2; i += 256) {
            int l = 2 * i;
            float s0 = 0.f, s1 = 0.f;
            #pragma unroll
            for (int k = 0; k < KERN; k++) {
                s0 += r[k] * sx[l + k];
                s1 += r[k] * sx[l + 1 + k];
            }
            cp2[i] = __floats2bfloat162_rn(s0 * al + be, s1 * al + be);
        }
    }
}

// ---------------- 256x128 bf16 mma.sync TN GEMM, f32 accum (gemm1, fc) ---------
#define KT 32
#define SROW (KT + 8)
template<bool BF16B>
__global__ __launch_bounds__(512) void k_wmma256(
    const __nv_bfloat16* __restrict__ A, int lda,
    const void* __restrict__ Bv, int ldb, int Nvalid, int Kvalid,
    float* __restrict__ C, long zStride, int ldc, int Kchunk)
{
    __shared__ __align__(16) __nv_bfloat16 sA[256 * SROW];
    __shared__ __align__(16) __nv_bfloat16 sB[128 * SROW];

    int t = threadIdx.x, lane = t & 31, wid = t >> 5;
    int wm = wid & 3, wn = wid >> 2;
    int m0 = blockIdx.x * 256, n0 = blockIdx.y * 128;
    long k0 = (long)blockIdx.z * Kchunk;

    int ra = t >> 1, ca = (t & 1) * 16;
    const __nv_bfloat16* Ag = A + (size_t)(m0 + ra) * lda + k0 + ca;
    int rb = t >> 2, cb = (t & 3) * 8;
    int nB = n0 + rb;
    const float* Bgf = (const float*)Bv + (size_t)nB * ldb + k0 + cb;
    const __nv_bfloat16* Bgh = (const __nv_bfloat16*)Bv + (size_t)nB * ldb + k0 + cb;
    bool nv = nB < Nvalid;

    uint32_t sA0 = smem_u32(sA), sB0 = smem_u32(sB);
    int rowA = lane & 15, colA = (lane >> 4) * 8;
    uint32_t uA[4];
    #pragma unroll
    for (int mt = 0; mt < 4; mt++)
        uA[mt] = sA0 + (uint32_t)((wm * 64 + mt * 16 + rowA) * SROW + colA) * 2u;
    uint32_t uB4[2];
    #pragma unroll
    for (int p = 0; p < 2; p++) {
        int row = wn * 32 + p * 16 + ((lane >> 4) & 1) * 8 + (lane & 7);
        int col = ((lane >> 3) & 1) * 8;
        uB4[p] = sB0 + (uint32_t)(row * SROW + col) * 2u;
    }

    float acc[4][4][4];
    #pragma unroll
    for (int i = 0; i < 4; i++)
        #pragma unroll
        for (int j = 0; j < 4; j++)
            #pragma unroll
            for (int q = 0; q < 4; q++) acc[i][j][q] = 0.f;

    const float4 zf = make_float4(0.f, 0.f, 0.f, 0.f);
    const uint4  zu = make_uint4(0u, 0u, 0u, 0u);
    uint4 pa0, pa1;
    float4 pb0, pb1;
    uint4 pbh;

    pa0 = *(const uint4*)Ag;
    pa1 = *(const uint4*)(Ag + 8);
    {
        bool kv = nv && (k0 + cb < Kvalid);
        if (BF16B) {
            pbh = kv ? *(const uint4*)Bgh : zu;
        } else {
            pb0 = kv ? *(const float4*)Bgf : zf;
            pb1 = kv ? *(const float4*)(Bgf + 4) : zf;
        }
    }

    for (int kb = 0; kb < Kchunk; kb += KT) {
        *(uint4*)&sA[ra * SROW + ca] = pa0;
        *(uint4*)&sA[ra * SROW + ca + 8] = pa1;
        if (BF16B) {
            *(uint4*)&sB[rb * SROW + cb] = pbh;
        } else {
            __nv_bfloat162 h0 = __float22bfloat162_rn(make_float2(pb0.x, pb0.y));
            __nv_bfloat162 h1 = __float22bfloat162_rn(make_float2(pb0.z, pb0.w));
            __nv_bfloat162 h2 = __float22bfloat162_rn(make_float2(pb1.x, pb1.y));
            __nv_bfloat162 h3 = __float22bfloat162_rn(make_float2(pb1.z, pb1.w));
            uint4 v;
            v.x = *(uint32_t*)&h0; v.y = *(uint32_t*)&h1;
            v.z = *(uint32_t*)&h2; v.w = *(uint32_t*)&h3;
            *(uint4*)&sB[rb * SROW + cb] = v;
        }
        __syncthreads();
        if (kb + KT < Kchunk) {
            int kn = kb + KT;
            pa0 = *(const uint4*)(Ag + kn);
            pa1 = *(const uint4*)(Ag + kn + 8);
            bool kv = nv && (k0 + kn + cb < Kvalid);
            if (BF16B) {
                pbh = kv ? *(const uint4*)(Bgh + kn) : zu;
            } else {
                pb0 = kv ? *(const float4*)(Bgf + kn) : zf;
                pb1 = kv ? *(const float4*)(Bgf + kn + 4) : zf;
            }
        }
        #pragma unroll
        for (int ks = 0; ks < 2; ks++) {
            uint32_t af[4][4], bq[2][4];
            #pragma unroll
            for (int mt = 0; mt < 4; mt++) ldsm_x4(af[mt], uA[mt] + ks * 32);
            #pragma unroll
            for (int p = 0; p < 2; p++) ldsm_x4(bq[p], uB4[p] + ks * 32);
            #pragma unroll
            for (int mt = 0; mt < 4; mt++)
                #pragma unroll
                for (int nt = 0; nt < 4; nt++)
                    mma_bf16(acc[mt][nt], af[mt], &bq[nt >> 1][(nt & 1) * 2]);
        }
        __syncthreads();
    }

    int gq = lane >> 2, gr = lane & 3;
    float* Cz = C + (long)blockIdx.z * zStride;
    #pragma unroll
    for (int mt = 0; mt < 4; mt++) {
        int m = m0 + wm * 64 + mt * 16 + gq;
        #pragma unroll
        for (int nt = 0; nt < 4; nt++) {
            int n = n0 + wn * 32 + nt * 8 + 2 * gr;
            if (n < Nvalid) {
                *(float2*)(Cz + (size_t)m * ldc + n) =
                    make_float2(acc[mt][nt][0], acc[mt][nt][1]);
                *(float2*)(Cz + (size_t)(m + 8) * ldc + n) =
                    make_float2(acc[mt][nt][2], acc[mt][nt][3]);
            }
        }
    }
}

// ---------------- 256x128 fp16 mma.sync TN GEMM, f16 accum + sigmoid (logits) --
__global__ __launch_bounds__(512) void k_wmma_h(
    const __half* __restrict__ A, int lda,
    const float* __restrict__ B, int ldb, int Nvalid, int Kvalid,
    float* __restrict__ C, int ldc, int Kchunk)
{
    __shared__ __align__(16) __half sA[256 * SROW];
    __shared__ __align__(16) __half sB[128 * SROW];

    int t = threadIdx.x, lane = t & 31, wid = t >> 5;
    int wm = wid & 3, wn = wid >> 2;
    int m0 = blockIdx.x * 256, n0 = blockIdx.y * 128;

    int ra = t >> 1, ca = (t & 1) * 16;
    const __half* Ag = A + (size_t)(m0 + ra) * lda + ca;
    int rb = t >> 2, cb = (t & 3) * 8;
    int nB = n0 + rb;
    const float* Bgf = B + (size_t)nB * ldb + cb;
    bool nv = nB < Nvalid;

    uint32_t sA0 = smem_u32(sA), sB0 = smem_u32(sB);
    int rowA = lane & 15, colA = (lane >> 4) * 8;
    uint32_t uA[4];
    #pragma unroll
    for (int mt = 0; mt < 4; mt++)
        uA[mt] = sA0 + (uint32_t)((wm * 64 + mt * 16 + rowA) * SROW + colA) * 2u;
    uint32_t uB4[2];
    #pragma unroll
    for (int p = 0; p < 2; p++) {
        int row = wn * 32 + p * 16 + ((lane >> 4) & 1) * 8 + (lane & 7);
        int col = ((lane >> 3) & 1) * 8;
        uB4[p] = sB0 + (uint32_t)(row * SROW + col) * 2u;
    }

    uint32_t acc[4][4][2];
    #pragma unroll
    for (int i = 0; i < 4; i++)
        #pragma unroll
        for (int j = 0; j < 4; j++) { acc[i][j][0] = 0u; acc[i][j][1] = 0u; }

    const float4 zf = make_float4(0.f, 0.f, 0.f, 0.f);
    uint4 pa0, pa1;
    float4 pb0, pb1;

    pa0 = *(const uint4*)Ag;
    pa1 = *(const uint4*)(Ag + 8);
    {
        bool kv = nv && (cb < Kvalid);
        pb0 = kv ? *(const float4*)Bgf : zf;
        pb1 = kv ? *(const float4*)(Bgf + 4) : zf;
    }

    for (int kb = 0; kb < Kchunk; kb += KT) {
        *(uint4*)&sA[ra * SROW + ca] = pa0;
        *(uint4*)&sA[ra * SROW + ca + 8] = pa1;
        {
            __half2 h0 = __float22half2_rn(make_float2(pb0.x, pb0.y));
            __half2 h1 = __float22half2_rn(make_float2(pb0.z, pb0.w));
            __half2 h2 = __float22half2_rn(make_float2(pb1.x, pb1.y));
            __half2 h3 = __float22half2_rn(make_float2(pb1.z, pb1.w));
            uint4 v;
            v.x = *(uint32_t*)&h0; v.y = *(uint32_t*)&h1;
            v.z = *(uint32_t*)&h2; v.w = *(uint32_t*)&h3;
            *(uint4*)&sB[rb * SROW + cb] = v;
        }
        __syncthreads();
        if (kb + KT < Kchunk) {
            int kn = kb + KT;
            pa0 = *(const uint4*)(Ag + kn);
            pa1 = *(const uint4*)(Ag + kn + 8);
            bool kv = nv && (kn + cb < Kvalid);
            pb0 = kv ? *(const float4*)(Bgf + kn) : zf;
            pb1 = kv ? *(const float4*)(Bgf + kn + 4) : zf;
        }
        #pragma unroll
        for (int ks = 0; ks < 2; ks++) {
            uint32_t af[4][4], bq[2][4];
            #pragma unroll
            for (int mt = 0; mt < 4; mt++) ldsm_x4(af[mt], uA[mt] + ks * 32);
            #pragma unroll
            for (int p = 0; p < 2; p++) ldsm_x4(bq[p], uB4[p] + ks * 32);
            #pragma unroll
            for (int mt = 0; mt < 4; mt++)
                #pragma unroll
                for (int nt = 0; nt < 4; nt++)
                    mma_f16acc(acc[mt][nt], af[mt], &bq[nt >> 1][(nt & 1) * 2]);
        }
        __syncthreads();
    }

    // epilogue: f16 accs -> float, sigmoid, store
    int gq = lane >> 2, gr = lane & 3;
    #pragma unroll
    for (int mt = 0; mt < 4; mt++) {
        int m = m0 + wm * 64 + mt * 16 + gq;
        #pragma unroll
        for (int nt = 0; nt < 4; nt++) {
            int n = n0 + wn * 32 + nt * 8 + 2 * gr;
            if (n < Nvalid) {
                float2 v0 = __half22float2(*(__half2*)&acc[mt][nt][0]);
                float2 v1 = __half22float2(*(__half2*)&acc[mt][nt][1]);
                v0.x = 1.f / (1.f + __expf(-v0.x));
                v0.y = 1.f / (1.f + __expf(-v0.y));
                v1.x = 1.f / (1.f + __expf(-v1.x));
                v1.y = 1.f / (1.f + __expf(-v1.y));
                *(float2*)(C + (size_t)m * ldc + n) = v0;
                *(float2*)(C + (size_t)(m + 8) * ldc + n) = v1;
            }
        }
    }
}

// ---------------- split-K reduce (float4), then bn2 + tanh -> fp16 (+K pad) -----
__global__ void k_redP() {
    int i4 = blockIdx.x * blockDim.x + threadIdx.x;
    if (i4 < BATCHN * IN_DIM / 4) {
        float4 y = make_float4(0.f, 0.f, 0.f, 0.f);
        const float4* P4 = (const float4*)g_Pf;
        for (int z = 0; z < ZSPLIT; z++) {
            float4 v = P4[(size_t)z * (BATCHN * IN_DIM / 4) + i4];
            y.x += v.x; y.y += v.y; y.z += v.z; y.w += v.w;
        }
        *(float4*)(g_y + i4 * 4) = y;
    }
}
__global__ void k_bn2(const float* __restrict__ g2, const float* __restrict__ b2) {
    int j = blockIdx.x, b = threadIdx.x;
    if (j >= IN_DIM) {
        g_zh[b * KPAD2 + j] = __float2half(0.f);
        return;
    }
    float y = g_y[b * IN_DIM + j];
    __shared__ float sr[32];
    float s1 = blockReduceSum(y, sr);
    float s2 = blockReduceSum(y * y, sr);
    float m = s1 * (1.f / BATCHN);
    float var = s2 * (1.f / BATCHN) - m * m;
    float zz = tanhf((y - m) * rsqrtf(var + EPSV) * g2[j] + b2[j]);
    g_zh[b * KPAD2 + j] = __float2half(zz);
}

// ---------------- launcher ----------------
extern "C" void kernel_launch(void* const* d_in, const int* in_sizes, int n_in,
                              void* d_out, int out_size) {
    const float* E   = (const float*)d_in[0];
    const float* R   = (const float*)d_in[1];
    const float* eW  = (const float*)d_in[2];
    const float* fcW = (const float*)d_in[3];
    const float* g0  = (const float*)d_in[4];
    const float* b0  = (const float*)d_in[5];
    const float* g1  = (const float*)d_in[6];
    const float* b1  = (const float*)d_in[7];
    const float* g2  = (const float*)d_in[8];
    const float* b2  = (const float*)d_in[9];
    const int*   e1  = (const int*)d_in[10];
    const int*   ri  = (const int*)d_in[11];
    float* out = (float*)d_out;

    float *xa, *Pf;
    cudaGetSymbolAddress((void**)&xa,  g_xa);
    cudaGetSymbolAddress((void**)&Pf,  g_Pf);
    __nv_bfloat16 *eWTb, *x0b, *cbf;
    __half* zh;
    cudaGetSymbolAddress((void**)&eWTb, g_eWTb);
    cudaGetSymbolAddress((void**)&x0b, g_x0b);
    cudaGetSymbolAddress((void**)&cbf, g_cbf);
    cudaGetSymbolAddress((void**)&zh,  g_zh);

    k_transpose<<<dim3((OUT_DIMX + 31) / 32, (IN_DIM + 31) / 32), dim3(32, 8)>>>(eW);
    k_bn0<<<KPAD2, BATCHN>>>(E, e1, g0, b0);

    // GEMM1 (bf16 HMMA f32-acc): [512,2000] = x0b @ eWTb^T
    k_wmma256<true><<<dim3(2, (OUT_DIMX + 127) / 128, 1), 512>>>(
        x0b, KPAD2, eWTb, IN_DIM, OUT_DIMX, IN_DIM,
        xa, 0L, OUT_DIMX, KPAD2);

    k_statsA<<<BATCHN, 256>>>(R, ri);
    k_statsB<<<OUT_CH, BATCHN>>>(g1, b1);
    k_conv<<<dim3(BATCHN, CSPLIT), 256>>>(R, ri);

    // fc GEMM (bf16 f32-acc): split-K 37 x 1728 = one 148-CTA wave
    k_wmma256<false><<<dim3(2, 2, ZSPLIT), 512>>>(
        cbf, FC_LENN, fcW, FC_LENN, IN_DIM, FC_LENN,
        Pf, (long)BATCHN * IN_DIM, IN_DIM, ZCHUNK);

    k_redP<<<(BATCHN * IN_DIM / 4 + 255) / 256, 256>>>();
    k_bn2<<<KPAD2, BATCHN>>>(g2, b2);

    // logits GEMM + sigmoid (fp16 HMMA f16-acc): [512,100000]
    k_wmma_h<<<dim3(2, (NUM_ENTSN + 127) / 128, 1), 512>>>(
        zh, KPAD2, E, IN_DIM, NUM_ENTSN, IN_DIM,
        out, NUM_ENTSN, KPAD2);

    (void)in_sizes; (void)n_in; (void)out_size;
}

// round 17
// speedup vs baseline: 1.0907x; 1.0907x over previous
#include <cuda_runtime.h>
#include <cuda_bf16.h>
#include <cuda_fp16.h>
#include <cstdint>

#define IN_DIM    200
#define OUT_DIMX  2000
#define BATCHN    512
#define OUT_CH    32
#define KERN      9
#define L_OUTN    1992
#define FC_LENN   (OUT_CH * L_OUTN)     // 63744
#define NUM_ENTSN 100000
#define EPSV      1e-5f
#define ZSPLIT    37                    // fc: grid (2,2,37) = 148 CTAs = 1 wave
#define ZCHUNK    1728
#define KPAD2     224

// ---------------- device scratch ----------------
__device__ __align__(128) __nv_bfloat16 g_eWTb[OUT_DIMX * IN_DIM];
__device__ __align__(128) __nv_bfloat16 g_x0b[BATCHN * KPAD2];
__device__ __align__(128) float g_xa [BATCHN * OUT_DIMX];
__device__ __align__(128) __nv_bfloat16 g_cbf[(size_t)BATCHN * FC_LENN + 512];
__device__ __align__(128) float g_Pf [(size_t)ZSPLIT * BATCHN * IN_DIM];
__device__ __align__(128) float g_y  [BATCHN * IN_DIM];
__device__ __align__(128) __half g_zh[BATCHN * KPAD2];
__device__ float g_s1[OUT_CH * BATCHN];
__device__ float g_s2[OUT_CH * BATCHN];
__device__ float g_alpha[OUT_CH];
__device__ float g_betap[OUT_CH];

// ---------------- helpers ----------------
__device__ __forceinline__ uint32_t smem_u32(const void* p) {
    uint32_t a;
    asm("{ .reg .u64 t; cvta.to.shared.u64 t, %1; cvt.u32.u64 %0, t; }" : "=r"(a) : "l"(p));
    return a;
}
__device__ __forceinline__ void ldsm_x4(uint32_t* r, uint32_t addr) {
    asm volatile("ldmatrix.sync.aligned.m8n8.x4.shared.b16 {%0,%1,%2,%3}, [%4];"
                 : "=r"(r[0]), "=r"(r[1]), "=r"(r[2]), "=r"(r[3]) : "r"(addr));
}
__device__ __forceinline__ void mma_bf16(float* c, const uint32_t* a, const uint32_t* b) {
    asm volatile("mma.sync.aligned.m16n8k16.row.col.f32.bf16.bf16.f32 "
                 "{%0,%1,%2,%3}, {%4,%5,%6,%7}, {%8,%9}, {%0,%1,%2,%3};"
                 : "+f"(c[0]), "+f"(c[1]), "+f"(c[2]), "+f"(c[3])
                 : "r"(a[0]), "r"(a[1]), "r"(a[2]), "r"(a[3]), "r"(b[0]), "r"(b[1]));
}
__device__ __forceinline__ void mma_f16acc(uint32_t* c, const uint32_t* a, const uint32_t* b) {
    asm volatile("mma.sync.aligned.m16n8k16.row.col.f16.f16.f16.f16 "
                 "{%0,%1}, {%2,%3,%4,%5}, {%6,%7}, {%0,%1};"
                 : "+r"(c[0]), "+r"(c[1])
                 : "r"(a[0]), "r"(a[1]), "r"(a[2]), "r"(a[3]), "r"(b[0]), "r"(b[1]));
}
__device__ __forceinline__ float fast_sigmoid(float x) {
    float t;
    asm("tanh.approx.f32 %0, %1;" : "=f"(t) : "f"(0.5f * x));
    return fmaf(0.5f, t, 0.5f);
}
__device__ __forceinline__ float blockReduceSum(float v, float* s) {
    __syncthreads();
    #pragma unroll
    for (int o = 16; o; o >>= 1) v += __shfl_down_sync(0xffffffffu, v, o);
    int w = threadIdx.x >> 5, l = threadIdx.x & 31;
    if (l == 0) s[w] = v;
    __syncthreads();
    int nw = blockDim.x >> 5;
    if (w == 0) {
        float r = (l < nw) ? s[l] : 0.f;
        #pragma unroll
        for (int o = 16; o; o >>= 1) r += __shfl_down_sync(0xffffffffu, r, o);
        if (l == 0) s[0] = r;
    }
    __syncthreads();
    return s[0];
}

// ---------------- tiled transpose: e_W -> bf16 eWT [2000,200] ------
__global__ void k_transpose(const float* __restrict__ W) {
    __shared__ float tile[32][33];
    int n0 = blockIdx.x * 32, k0 = blockIdx.y * 32;
    int tx = threadIdx.x, ty = threadIdx.y;
    #pragma unroll
    for (int dy = 0; dy < 32; dy += 8) {
        int k = k0 + ty + dy, n = n0 + tx;
        tile[ty + dy][tx] = (k < IN_DIM && n < OUT_DIMX) ? W[k * OUT_DIMX + n] : 0.f;
    }
    __syncthreads();
    #pragma unroll
    for (int dy = 0; dy < 32; dy += 8) {
        int n = n0 + ty + dy, k = k0 + tx;
        if (n < OUT_DIMX && k < IN_DIM)
            g_eWTb[n * IN_DIM + k] = __float2bfloat16(tile[tx][ty + dy]);
    }
}

// ---------------- gather + bn0 -> bf16 padded ----------------
__global__ void k_bn0(const float* __restrict__ E, const int* __restrict__ e1,
                      const float* __restrict__ g, const float* __restrict__ bt) {
    int f = blockIdx.x, b = threadIdx.x;
    if (f >= IN_DIM) {
        g_x0b[b * KPAD2 + f] = __nv_bfloat16(0.f);
        return;
    }
    float v = E[(size_t)e1[b] * IN_DIM + f];
    __shared__ float sr[32];
    float s1 = blockReduceSum(v, sr);
    float s2 = blockReduceSum(v * v, sr);
    float m = s1 * (1.f / BATCHN);
    float var = s2 * (1.f / BATCHN) - m * m;
    g_x0b[b * KPAD2 + f] =
        __float2bfloat16((v - m) * rsqrtf(var + EPSV) * g[f] + bt[f]);
}

// ---------------- bn1 stats via windowed autocorrelation ----------
__global__ __launch_bounds__(256) void k_statsA(const float* __restrict__ R,
                                                const int* __restrict__ ridx) {
    int b = blockIdx.x, t = threadIdx.x;
    __shared__ __align__(16) float sx[OUT_DIMX];
    __shared__ float red[8][54];
    __shared__ float TG[54];
    for (int i = t; i < OUT_DIMX; i += 256) sx[i] = g_xa[(size_t)b * OUT_DIMX + i];
    __syncthreads();
    float acc[54];
    #pragma unroll
    for (int i = 0; i < 54; i++) acc[i] = 0.f;
    for (int grp = t; grp < L_OUTN / 4; grp += 256) {
        int l4 = grp * 4;
        float w[12];
        float4 v0 = *(const float4*)(sx + l4);
        float4 v1 = *(const float4*)(sx + l4 + 4);
        float4 v2 = *(const float4*)(sx + l4 + 8);
        w[0]=v0.x; w[1]=v0.y; w[2]=v0.z; w[3]=v0.w;
        w[4]=v1.x; w[5]=v1.y; w[6]=v1.z; w[7]=v1.w;
        w[8]=v2.x; w[9]=v2.y; w[10]=v2.z; w[11]=v2.w;
        #pragma unroll
        for (int j = 0; j < 4; j++) {
            #pragma unroll
            for (int k = 0; k < KERN; k++) acc[k] += w[j + k];
            int p = 9;
            #pragma unroll
            for (int k = 0; k < KERN; k++)
                #pragma unroll
                for (int k2 = k; k2 < KERN; k2++) acc[p++] += w[j + k] * w[j + k2];
        }
    }
    #pragma unroll
    for (int i = 0; i < 54; i++) {
        float v = acc[i];
        #pragma unroll
        for (int o = 16; o; o >>= 1) v += __shfl_down_sync(0xffffffffu, v, o);
        if ((t & 31) == 0) red[t >> 5][i] = v;
    }
    __syncthreads();
    if (t < 54) {
        float s = 0.f;
        #pragma unroll
        for (int w2 = 0; w2 < 8; w2++) s += red[w2][t];
        TG[t] = s;
    }
    __syncthreads();
    if (t < OUT_CH) {
        const float* Rb = R + (size_t)ridx[b] * OUT_CH * KERN + t * KERN;
        float r[KERN];
        #pragma unroll
        for (int k = 0; k < KERN; k++) r[k] = Rb[k];
        float s1 = 0.f, s2 = 0.f;
        #pragma unroll
        for (int k = 0; k < KERN; k++) s1 += r[k] * TG[k];
        int p = 9;
        #pragma unroll
        for (int k = 0; k < KERN; k++)
            #pragma unroll
            for (int k2 = k; k2 < KERN; k2++) {
                float c = (k2 == k) ? 1.f : 2.f;
                s2 += c * r[k] * r[k2] * TG[p++];
            }
        g_s1[t * BATCHN + b] = s1;
        g_s2[t * BATCHN + b] = s2;
    }
}
__global__ void k_statsB(const float* __restrict__ g1, const float* __restrict__ b1) {
    int o = blockIdx.x;
    __shared__ float sr[32];
    float s1 = blockReduceSum(g_s1[o * BATCHN + threadIdx.x], sr);
    float s2 = blockReduceSum(g_s2[o * BATCHN + threadIdx.x], sr);
    if (threadIdx.x == 0) {
        float Nf = (float)BATCHN * (float)L_OUTN;
        float m = s1 / Nf;
        float var = s2 / Nf - m * m;
        float a = rsqrtf(var + EPSV) * g1[o];
        g_alpha[o] = a;
        g_betap[o] = b1[o] - m * a;
    }
}

// ---------------- conv1d + bn1-affine -> bf16 (channel-split x8) ----
#define CSPLIT 8
#define CH_PER (OUT_CH / CSPLIT)
__global__ __launch_bounds__(256) void k_conv(const float* __restrict__ R,
                                              const int* __restrict__ ridx) {
    int b = blockIdx.x;
    int o0 = blockIdx.y * CH_PER;
    __shared__ float sx[OUT_DIMX];
    for (int i = threadIdx.x; i < OUT_DIMX; i += 256)
        sx[i] = g_xa[(size_t)b * OUT_DIMX + i];
    __syncthreads();
    const float* Rb = R + (size_t)ridx[b] * OUT_CH * KERN;
    #pragma unroll
    for (int oo = 0; oo < CH_PER; oo++) {
        int o = o0 + oo;
        float r[KERN];
        #pragma unroll
        for (int k = 0; k < KERN; k++) r[k] = Rb[o * KERN + k];
        float al = g_alpha[o], be = g_betap[o];
        __nv_bfloat162* cp2 = (__nv_bfloat162*)(g_cbf + (size_t)b * FC_LENN + o * L_OUTN);
        for (int i = threadIdx.x; i < L_OUTN / 2; i += 256) {
            int l = 2 * i;
            float s0 = 0.f, s1 = 0.f;
            #pragma unroll
            for (int k = 0; k < KERN; k++) {
                s0 += r[k] * sx[l + k];
                s1 += r[k] * sx[l + 1 + k];
            }
            cp2[i] = __floats2bfloat162_rn(s0 * al + be, s1 * al + be);
        }
    }
}

// ---------------- 256x128 bf16 mma.sync TN GEMM, f32 accum (gemm1, fc) ---------
// K trimmed per CTA: kend16 = min(Kchunk, align16(Kvalid - k0)); 16-wide tail.
#define KT 32
#define SROW (KT + 8)
template<bool BF16B>
__global__ __launch_bounds__(512) void k_wmma256(
    const __nv_bfloat16* __restrict__ A, int lda,
    const void* __restrict__ Bv, int ldb, int Nvalid, int Kvalid,
    float* __restrict__ C, long zStride, int ldc, int Kchunk)
{
    __shared__ __align__(16) __nv_bfloat16 sA[256 * SROW];
    __shared__ __align__(16) __nv_bfloat16 sB[128 * SROW];

    int t = threadIdx.x, lane = t & 31, wid = t >> 5;
    int wm = wid & 3, wn = wid >> 2;
    int m0 = blockIdx.x * 256, n0 = blockIdx.y * 128;
    long k0 = (long)blockIdx.z * Kchunk;

    int krem = (int)((long)Kvalid - k0);
    int kend16 = ((krem + 15) & ~15);
    if (kend16 > Kchunk) kend16 = Kchunk;
    int kend32 = kend16 & ~31;
    bool tail = (kend16 & 16) != 0;

    int ra = t >> 1, ca = (t & 1) * 16;
    const __nv_bfloat16* Ag = A + (size_t)(m0 + ra) * lda + k0 + ca;
    int rb = t >> 2, cb = (t & 3) * 8;
    int nB = n0 + rb;
    const float* Bgf = (const float*)Bv + (size_t)nB * ldb + k0 + cb;
    const __nv_bfloat16* Bgh = (const __nv_bfloat16*)Bv + (size_t)nB * ldb + k0 + cb;
    bool nv = nB < Nvalid;

    uint32_t sA0 = smem_u32(sA), sB0 = smem_u32(sB);
    int rowA = lane & 15, colA = (lane >> 4) * 8;
    uint32_t uA[4];
    #pragma unroll
    for (int mt = 0; mt < 4; mt++)
        uA[mt] = sA0 + (uint32_t)((wm * 64 + mt * 16 + rowA) * SROW + colA) * 2u;
    uint32_t uB4[2];
    #pragma unroll
    for (int p = 0; p < 2; p++) {
        int row = wn * 32 + p * 16 + ((lane >> 4) & 1) * 8 + (lane & 7);
        int col = ((lane >> 3) & 1) * 8;
        uB4[p] = sB0 + (uint32_t)(row * SROW + col) * 2u;
    }

    float acc[4][4][4];
    #pragma unroll
    for (int i = 0; i < 4; i++)
        #pragma unroll
        for (int j = 0; j < 4; j++)
            #pragma unroll
            for (int q = 0; q < 4; q++) acc[i][j][q] = 0.f;

    const float4 zf = make_float4(0.f, 0.f, 0.f, 0.f);
    const uint4  zu = make_uint4(0u, 0u, 0u, 0u);
    uint4 pa0, pa1;
    float4 pb0, pb1;
    uint4 pbh;

    pa0 = *(const uint4*)Ag;
    pa1 = *(const uint4*)(Ag + 8);
    {
        bool kv = nv && (k0 + cb < Kvalid);
        if (BF16B) {
            pbh = kv ? *(const uint4*)Bgh : zu;
        } else {
            pb0 = kv ? *(const float4*)Bgf : zf;
            pb1 = kv ? *(const float4*)(Bgf + 4) : zf;
        }
    }

    for (int kb = 0; kb < kend32; kb += KT) {
        *(uint4*)&sA[ra * SROW + ca] = pa0;
        *(uint4*)&sA[ra * SROW + ca + 8] = pa1;
        if (BF16B) {
            *(uint4*)&sB[rb * SROW + cb] = pbh;
        } else {
            __nv_bfloat162 h0 = __float22bfloat162_rn(make_float2(pb0.x, pb0.y));
            __nv_bfloat162 h1 = __float22bfloat162_rn(make_float2(pb0.z, pb0.w));
            __nv_bfloat162 h2 = __float22bfloat162_rn(make_float2(pb1.x, pb1.y));
            __nv_bfloat162 h3 = __float22bfloat162_rn(make_float2(pb1.z, pb1.w));
            uint4 v;
            v.x = *(uint32_t*)&h0; v.y = *(uint32_t*)&h1;
            v.z = *(uint32_t*)&h2; v.w = *(uint32_t*)&h3;
            *(uint4*)&sB[rb * SROW + cb] = v;
        }
        __syncthreads();
        if (kb + KT < kend16) {
            int kn = kb + KT;
            pa0 = *(const uint4*)(Ag + kn);
            pa1 = *(const uint4*)(Ag + kn + 8);
            bool kv = nv && (k0 + kn + cb < Kvalid);
            if (BF16B) {
                pbh = kv ? *(const uint4*)(Bgh + kn) : zu;
            } else {
                pb0 = kv ? *(const float4*)(Bgf + kn) : zf;
                pb1 = kv ? *(const float4*)(Bgf + kn + 4) : zf;
            }
        }
        #pragma unroll
        for (int ks = 0; ks < 2; ks++) {
            uint32_t af[4][4], bq[2][4];
            #pragma unroll
            for (int mt = 0; mt < 4; mt++) ldsm_x4(af[mt], uA[mt] + ks * 32);
            #pragma unroll
            for (int p = 0; p < 2; p++) ldsm_x4(bq[p], uB4[p] + ks * 32);
            #pragma unroll
            for (int mt = 0; mt < 4; mt++)
                #pragma unroll
                for (int nt = 0; nt < 4; nt++)
                    mma_bf16(acc[mt][nt], af[mt], &bq[nt >> 1][(nt & 1) * 2]);
        }
        __syncthreads();
    }
    if (tail) {
        *(uint4*)&sA[ra * SROW + ca] = pa0;
        *(uint4*)&sA[ra * SROW + ca + 8] = pa1;
        if (BF16B) {
            *(uint4*)&sB[rb * SROW + cb] = pbh;
        } else {
            __nv_bfloat162 h0 = __float22bfloat162_rn(make_float2(pb0.x, pb0.y));
            __nv_bfloat162 h1 = __float22bfloat162_rn(make_float2(pb0.z, pb0.w));
            __nv_bfloat162 h2 = __float22bfloat162_rn(make_float2(pb1.x, pb1.y));
            __nv_bfloat162 h3 = __float22bfloat162_rn(make_float2(pb1.z, pb1.w));
            uint4 v;
            v.x = *(uint32_t*)&h0; v.y = *(uint32_t*)&h1;
            v.z = *(uint32_t*)&h2; v.w = *(uint32_t*)&h3;
            *(uint4*)&sB[rb * SROW + cb] = v;
        }
        __syncthreads();
        uint32_t af[4][4], bq[2][4];
        #pragma unroll
        for (int mt = 0; mt < 4; mt++) ldsm_x4(af[mt], uA[mt]);
        #pragma unroll
        for (int p = 0; p < 2; p++) ldsm_x4(bq[p], uB4[p]);
        #pragma unroll
        for (int mt = 0; mt < 4; mt++)
            #pragma unroll
            for (int nt = 0; nt < 4; nt++)
                mma_bf16(acc[mt][nt], af[mt], &bq[nt >> 1][(nt & 1) * 2]);
    }

    int gq = lane >> 2, gr = lane & 3;
    float* Cz = C + (long)blockIdx.z * zStride;
    #pragma unroll
    for (int mt = 0; mt < 4; mt++) {
        int m = m0 + wm * 64 + mt * 16 + gq;
        #pragma unroll
        for (int nt = 0; nt < 4; nt++) {
            int n = n0 + wn * 32 + nt * 8 + 2 * gr;
            if (n < Nvalid) {
                *(float2*)(Cz + (size_t)m * ldc + n) =
                    make_float2(acc[mt][nt][0], acc[mt][nt][1]);
                *(float2*)(Cz + (size_t)(m + 8) * ldc + n) =
                    make_float2(acc[mt][nt][2], acc[mt][nt][3]);
            }
        }
    }
}

// ---------------- 256x128 fp16 mma.sync TN GEMM, f16 accum + sigmoid (logits) --
__global__ __launch_bounds__(512) void k_wmma_h(
    const __half* __restrict__ A, int lda,
    const float* __restrict__ B, int ldb, int Nvalid, int Kvalid,
    float* __restrict__ C, int ldc)
{
    __shared__ __align__(16) __half sA[256 * SROW];
    __shared__ __align__(16) __half sB[128 * SROW];

    int t = threadIdx.x, lane = t & 31, wid = t >> 5;
    int wm = wid & 3, wn = wid >> 2;
    int m0 = blockIdx.x * 256, n0 = blockIdx.y * 128;

    int kend16 = (Kvalid + 15) & ~15;      // 208
    int kend32 = kend16 & ~31;             // 192
    bool tail = (kend16 & 16) != 0;        // true

    int ra = t >> 1, ca = (t & 1) * 16;
    const __half* Ag = A + (size_t)(m0 + ra) * lda + ca;
    int rb = t >> 2, cb = (t & 3) * 8;
    int nB = n0 + rb;
    const float* Bgf = B + (size_t)nB * ldb + cb;
    bool nv = nB < Nvalid;

    uint32_t sA0 = smem_u32(sA), sB0 = smem_u32(sB);
    int rowA = lane & 15, colA = (lane >> 4) * 8;
    uint32_t uA[4];
    #pragma unroll
    for (int mt = 0; mt < 4; mt++)
        uA[mt] = sA0 + (uint32_t)((wm * 64 + mt * 16 + rowA) * SROW + colA) * 2u;
    uint32_t uB4[2];
    #pragma unroll
    for (int p = 0; p < 2; p++) {
        int row = wn * 32 + p * 16 + ((lane >> 4) & 1) * 8 + (lane & 7);
        int col = ((lane >> 3) & 1) * 8;
        uB4[p] = sB0 + (uint32_t)(row * SROW + col) * 2u;
    }

    uint32_t acc[4][4][2];
    #pragma unroll
    for (int i = 0; i < 4; i++)
        #pragma unroll
        for (int j = 0; j < 4; j++) { acc[i][j][0] = 0u; acc[i][j][1] = 0u; }

    const float4 zf = make_float4(0.f, 0.f, 0.f, 0.f);
    uint4 pa0, pa1;
    float4 pb0, pb1;

    pa0 = *(const uint4*)Ag;
    pa1 = *(const uint4*)(Ag + 8);
    {
        bool kv = nv && (cb < Kvalid);
        pb0 = kv ? *(const float4*)Bgf : zf;
        pb1 = kv ? *(const float4*)(Bgf + 4) : zf;
    }

    for (int kb = 0; kb < kend32; kb += KT) {
        *(uint4*)&sA[ra * SROW + ca] = pa0;
        *(uint4*)&sA[ra * SROW + ca + 8] = pa1;
        {
            __half2 h0 = __float22half2_rn(make_float2(pb0.x, pb0.y));
            __half2 h1 = __float22half2_rn(make_float2(pb0.z, pb0.w));
            __half2 h2 = __float22half2_rn(make_float2(pb1.x, pb1.y));
            __half2 h3 = __float22half2_rn(make_float2(pb1.z, pb1.w));
            uint4 v;
            v.x = *(uint32_t*)&h0; v.y = *(uint32_t*)&h1;
            v.z = *(uint32_t*)&h2; v.w = *(uint32_t*)&h3;
            *(uint4*)&sB[rb * SROW + cb] = v;
        }
        __syncthreads();
        if (kb + KT < kend16) {
            int kn = kb + KT;
            pa0 = *(const uint4*)(Ag + kn);
            pa1 = *(const uint4*)(Ag + kn + 8);
            bool kv = nv && (kn + cb < Kvalid);
            pb0 = kv ? *(const float4*)(Bgf + kn) : zf;
            pb1 = kv ? *(const float4*)(Bgf + kn + 4) : zf;
        }
        #pragma unroll
        for (int ks = 0; ks < 2; ks++) {
            uint32_t af[4][4], bq[2][4];
            #pragma unroll
            for (int mt = 0; mt < 4; mt++) ldsm_x4(af[mt], uA[mt] + ks * 32);
            #pragma unroll
            for (int p = 0; p < 2; p++) ldsm_x4(bq[p], uB4[p] + ks * 32);
            #pragma unroll
            for (int mt = 0; mt < 4; mt++)
                #pragma unroll
                for (int nt = 0; nt < 4; nt++)
                    mma_f16acc(acc[mt][nt], af[mt], &bq[nt >> 1][(nt & 1) * 2]);
        }
        __syncthreads();
    }
    if (tail) {
        *(uint4*)&sA[ra * SROW + ca] = pa0;
        *(uint4*)&sA[ra * SROW + ca + 8] = pa1;
        {
            __half2 h0 = __float22half2_rn(make_float2(pb0.x, pb0.y));
            __half2 h1 = __float22half2_rn(make_float2(pb0.z, pb0.w));
            __half2 h2 = __float22half2_rn(make_float2(pb1.x, pb1.y));
            __half2 h3 = __float22half2_rn(make_float2(pb1.z, pb1.w));
            uint4 v;
            v.x = *(uint32_t*)&h0; v.y = *(uint32_t*)&h1;
            v.z = *(uint32_t*)&h2; v.w = *(uint32_t*)&h3;
            *(uint4*)&sB[rb * SROW + cb] = v;
        }
        __syncthreads();
        uint32_t af[4][4], bq[2][4];
        #pragma unroll
        for (int mt = 0; mt < 4; mt++) ldsm_x4(af[mt], uA[mt]);
        #pragma unroll
        for (int p = 0; p < 2; p++) ldsm_x4(bq[p], uB4[p]);
        #pragma unroll
        for (int mt = 0; mt < 4; mt++)
            #pragma unroll
            for (int nt = 0; nt < 4; nt++)
                mma_f16acc(acc[mt][nt], af[mt], &bq[nt >> 1][(nt & 1) * 2]);
    }

    // epilogue: f16 accs -> float, fast sigmoid, store
    int gq = lane >> 2, gr = lane & 3;
    #pragma unroll
    for (int mt = 0; mt < 4; mt++) {
        int m = m0 + wm * 64 + mt * 16 + gq;
        #pragma unroll
        for (int nt = 0; nt < 4; nt++) {
            int n = n0 + wn * 32 + nt * 8 + 2 * gr;
            if (n < Nvalid) {
                float2 v0 = __half22float2(*(__half2*)&acc[mt][nt][0]);
                float2 v1 = __half22float2(*(__half2*)&acc[mt][nt][1]);
                v0.x = fast_sigmoid(v0.x);
                v0.y = fast_sigmoid(v0.y);
                v1.x = fast_sigmoid(v1.x);
                v1.y = fast_sigmoid(v1.y);
                *(float2*)(C + (size_t)m * ldc + n) = v0;
                *(float2*)(C + (size_t)(m + 8) * ldc + n) = v1;
            }
        }
    }
}

// ---------------- split-K reduce (float4), then bn2 + tanh -> fp16 (+K pad) -----
__global__ void k_redP() {
    int i4 = blockIdx.x * blockDim.x + threadIdx.x;
    if (i4 < BATCHN * IN_DIM / 4) {
        float4 y = make_float4(0.f, 0.f, 0.f, 0.f);
        const float4* P4 = (const float4*)g_Pf;
        for (int z = 0; z < ZSPLIT; z++) {
            float4 v = P4[(size_t)z * (BATCHN * IN_DIM / 4) + i4];
            y.x += v.x; y.y += v.y; y.z += v.z; y.w += v.w;
        }
        *(float4*)(g_y + i4 * 4) = y;
    }
}
__global__ void k_bn2(const float* __restrict__ g2, const float* __restrict__ b2) {
    int j = blockIdx.x, b = threadIdx.x;
    if (j >= IN_DIM) {
        g_zh[b * KPAD2 + j] = __float2half(0.f);
        return;
    }
    float y = g_y[b * IN_DIM + j];
    __shared__ float sr[32];
    float s1 = blockReduceSum(y, sr);
    float s2 = blockReduceSum(y * y, sr);
    float m = s1 * (1.f / BATCHN);
    float var = s2 * (1.f / BATCHN) - m * m;
    float zz = tanhf((y - m) * rsqrtf(var + EPSV) * g2[j] + b2[j]);
    g_zh[b * KPAD2 + j] = __float2half(zz);
}

// ---------------- launcher ----------------
extern "C" void kernel_launch(void* const* d_in, const int* in_sizes, int n_in,
                              void* d_out, int out_size) {
    const float* E   = (const float*)d_in[0];
    const float* R   = (const float*)d_in[1];
    const float* eW  = (const float*)d_in[2];
    const float* fcW = (const float*)d_in[3];
    const float* g0  = (const float*)d_in[4];
    const float* b0  = (const float*)d_in[5];
    const float* g1  = (const float*)d_in[6];
    const float* b1  = (const float*)d_in[7];
    const float* g2  = (const float*)d_in[8];
    const float* b2  = (const float*)d_in[9];
    const int*   e1  = (const int*)d_in[10];
    const int*   ri  = (const int*)d_in[11];
    float* out = (float*)d_out;

    float *xa, *Pf;
    cudaGetSymbolAddress((void**)&xa,  g_xa);
    cudaGetSymbolAddress((void**)&Pf,  g_Pf);
    __nv_bfloat16 *eWTb, *x0b, *cbf;
    __half* zh;
    cudaGetSymbolAddress((void**)&eWTb, g_eWTb);
    cudaGetSymbolAddress((void**)&x0b, g_x0b);
    cudaGetSymbolAddress((void**)&cbf, g_cbf);
    cudaGetSymbolAddress((void**)&zh,  g_zh);

    k_transpose<<<dim3((OUT_DIMX + 31) / 32, (IN_DIM + 31) / 32), dim3(32, 8)>>>(eW);
    k_bn0<<<KPAD2, BATCHN>>>(E, e1, g0, b0);

    // GEMM1 (bf16 f32-acc): K trimmed to 208 effective
    k_wmma256<true><<<dim3(2, (OUT_DIMX + 127) / 128, 1), 512>>>(
        x0b, KPAD2, eWTb, IN_DIM, OUT_DIMX, IN_DIM,
        xa, 0L, OUT_DIMX, KPAD2);

    k_statsA<<<BATCHN, 256>>>(R, ri);
    k_statsB<<<OUT_CH, BATCHN>>>(g1, b1);
    k_conv<<<dim3(BATCHN, CSPLIT), 256>>>(R, ri);

    // fc GEMM (bf16 f32-acc): one 148-CTA wave; last z trimmed 54->48 iters
    k_wmma256<false><<<dim3(2, 2, ZSPLIT), 512>>>(
        cbf, FC_LENN, fcW, FC_LENN, IN_DIM, FC_LENN,
        Pf, (long)BATCHN * IN_DIM, IN_DIM, ZCHUNK);

    k_redP<<<(BATCHN * IN_DIM / 4 + 255) / 256, 256>>>();
    k_bn2<<<KPAD2, BATCHN>>>(g2, b2);

    // logits GEMM + fast sigmoid (fp16 f16-acc): K 224 -> 208 effective
    k_wmma_h<<<dim3(2, (NUM_ENTSN + 127) / 128, 1), 512>>>(
        zh, KPAD2, E, IN_DIM, NUM_ENTSN, IN_DIM,
        out, NUM_ENTSN);

    (void)in_sizes; (void)n_in; (void)out_size;
}